// round 2
// baseline (speedup 1.0000x reference)
#include <cuda_runtime.h>

#define NPTS   2000000
#define NCOMP  48
#define G      300
#define TBLF   (G * NCOMP)                 // 14400 floats per table (dense [G][48])
#define TBL3   (3 * TBLF)                  // 43200 floats
#define BLK    512
#define WARPS  (BLK / 32)                  // 16
#define SSTR   17                          // staging row stride (floats)
#define STAGEW (NCOMP * SSTR)              // 816 floats per warp
#define SMEM_BYTES ((TBL3 + WARPS * STAGEW) * 4)   // 225024 B
#define NBLOCKS 152
#define TILES  (NPTS / 16)                 // 125000 (exact)

__device__ float g_pT[TBL3];

// Transpose each param [C=48, G=300] -> dense [G][48].
__global__ void cp_prep(const float* __restrict__ p0,
                        const float* __restrict__ p1,
                        const float* __restrict__ p2) {
    int idx = blockIdx.x * blockDim.x + threadIdx.x;
    if (idx >= TBL3) return;
    int t   = idx / TBLF;
    int rem = idx - t * TBLF;
    int g   = rem / NCOMP;
    int c   = rem - g * NCOMP;
    const float* p = (t == 0) ? p0 : ((t == 1) ? p1 : p2);
    g_pT[idx] = p[c * G + g];
}

// Per-dim conflict-free fetch + interp. 8 lanes (j=0..7) serve one point.
// Returns v (chunk j: comps 4j..4j+3) and ve (chunk 8+(j&3): comps 32+4(j&3)..).
__device__ __forceinline__ void interp_dim(const float4* __restrict__ T4,
                                           int base4_0, int base4_1,
                                           float w, int j, bool jlow,
                                           float4& v, float4& ve) {
    float4 a0 = T4[base4_0 + j];                       // tap0 chunks 0..7
    float4 a1 = T4[base4_1 + j];                       // tap1 chunks 0..7
    int eidx  = jlow ? (base4_0 + 8 + j) : (base4_1 + 4 + j);
    float4 ae = T4[eidx];                              // mixed extras, conflict-free

    v.x = fmaf(w, a1.x - a0.x, a0.x);
    v.y = fmaf(w, a1.y - a0.y, a0.y);
    v.z = fmaf(w, a1.z - a0.z, a0.z);
    v.w = fmaf(w, a1.w - a0.w, a0.w);

    float4 ao;
    ao.x = __shfl_xor_sync(0xffffffffu, ae.x, 4);
    ao.y = __shfl_xor_sync(0xffffffffu, ae.y, 4);
    ao.z = __shfl_xor_sync(0xffffffffu, ae.z, 4);
    ao.w = __shfl_xor_sync(0xffffffffu, ae.w, 4);

    // jlow lanes hold tap0-extra, high lanes hold tap1-extra.
    float4 t0e, t1e;
    t0e.x = jlow ? ae.x : ao.x;  t1e.x = jlow ? ao.x : ae.x;
    t0e.y = jlow ? ae.y : ao.y;  t1e.y = jlow ? ao.y : ae.y;
    t0e.z = jlow ? ae.z : ao.z;  t1e.z = jlow ? ao.z : ae.z;
    t0e.w = jlow ? ae.w : ao.w;  t1e.w = jlow ? ao.w : ae.w;

    ve.x = fmaf(w, t1e.x - t0e.x, t0e.x);
    ve.y = fmaf(w, t1e.y - t0e.y, t0e.y);
    ve.z = fmaf(w, t1e.z - t0e.z, t0e.z);
    ve.w = fmaf(w, t1e.w - t0e.w, t0e.w);
}

__global__ __launch_bounds__(BLK) void cp_eval(const float* __restrict__ xyz,
                                               float* __restrict__ out) {
    extern __shared__ float sh[];
    // One-time cooperative table load (persistent blocks), 16B vectors.
    {
        const float4* src = (const float4*)g_pT;
        float4* dst = (float4*)sh;
        for (int i = threadIdx.x; i < TBL3 / 4; i += BLK) dst[i] = src[i];
    }
    __syncthreads();

    const int lane = threadIdx.x & 31;
    const int warp = threadIdx.x >> 5;
    const int j    = lane & 7;          // chunk lane within point group
    const int pg   = lane >> 3;         // point group 0..3
    const bool jlow = (j < 4);

    const float4* T4 = (const float4*)sh;
    float* stg = sh + TBL3 + warp * STAGEW;

    const int gw = blockIdx.x * WARPS + warp;
    const int ph = lane >> 4;           // readback: component parity half
    const int pp = lane & 15;           // readback: point within tile

    for (int tile = gw; tile < TILES; tile += NBLOCKS * WARPS) {
        const int n0 = tile * 16;

        #pragma unroll 1
        for (int s = 0; s < 4; s++) {
            const int p16 = s * 4 + pg;
            const int n   = n0 + p16;

            float x = __ldg(xyz + 3 * n + 0);
            float y = __ldg(xyz + 3 * n + 1);
            float z = __ldg(xyz + 3 * n + 2);

            float px = (x + 1.0f) * 0.5f * (float)(G - 1);
            float py = (y + 1.0f) * 0.5f * (float)(G - 1);
            float pz = (z + 1.0f) * 0.5f * (float)(G - 1);

            int i0x = min(max((int)floorf(px), 0), G - 1);
            int i0y = min(max((int)floorf(py), 0), G - 1);
            int i0z = min(max((int)floorf(pz), 0), G - 1);
            int i1x = min(i0x + 1, G - 1);
            int i1y = min(i0y + 1, G - 1);
            int i1z = min(i0z + 1, G - 1);

            float wx = px - (float)i0x;
            float wy = py - (float)i0y;
            float wz = pz - (float)i0z;

            // float4 base indices: table d at float offset d*TBLF, row r at 48*r.
            int bx0 = 0 * (TBLF / 4) + 12 * i0x, bx1 = 0 * (TBLF / 4) + 12 * i1x;
            int by0 = 1 * (TBLF / 4) + 12 * i0y, by1 = 1 * (TBLF / 4) + 12 * i1y;
            int bz0 = 2 * (TBLF / 4) + 12 * i0z, bz1 = 2 * (TBLF / 4) + 12 * i1z;

            float4 vx, vxe, vy, vye, vz, vze;
            interp_dim(T4, bx0, bx1, wx, j, jlow, vx, vxe);
            interp_dim(T4, by0, by1, wy, j, jlow, vy, vye);
            interp_dim(T4, bz0, bz1, wz, j, jlow, vz, vze);

            float4 f, fe;
            f.x = vx.x * vy.x * vz.x;   f.y = vx.y * vy.y * vz.y;
            f.z = vx.z * vy.z * vz.z;   f.w = vx.w * vy.w * vz.w;
            fe.x = vxe.x * vye.x * vze.x;  fe.y = vxe.y * vye.y * vze.y;
            fe.z = vxe.z * vye.z * vze.z;  fe.w = vxe.w * vye.w * vze.w;

            // Stage: main chunks (comps 4j..4j+3), conflict-free banks (4j+17p).
            stg[(4 * j + 0) * SSTR + p16] = f.x;
            stg[(4 * j + 1) * SSTR + p16] = f.y;
            stg[(4 * j + 2) * SSTR + p16] = f.z;
            stg[(4 * j + 3) * SSTR + p16] = f.w;
            if (jlow) {                 // extras: comps 32+4j..35+4j
                stg[(32 + 4 * j + 0) * SSTR + p16] = fe.x;
                stg[(32 + 4 * j + 1) * SSTR + p16] = fe.y;
                stg[(32 + 4 * j + 2) * SSTR + p16] = fe.z;
                stg[(32 + 4 * j + 3) * SSTR + p16] = fe.w;
            }
        }
        __syncwarp();

        // Coalesced writeback: half-warp per component row, 64B runs.
        #pragma unroll
        for (int t = 0; t < 24; t++) {
            int c = 2 * t + ph;
            out[c * NPTS + n0 + pp] = stg[c * SSTR + pp];
        }
        __syncwarp();   // staging reused next tile
    }
}

extern "C" void kernel_launch(void* const* d_in, const int* in_sizes, int n_in,
                              void* d_out, int out_size) {
    const float* xyz = (const float*)d_in[0];
    const float* p0  = (const float*)d_in[1];
    const float* p1  = (const float*)d_in[2];
    const float* p2  = (const float*)d_in[3];
    float* out = (float*)d_out;

    cp_prep<<<(TBL3 + 255) / 256, 256>>>(p0, p1, p2);

    static bool attr_set = false;
    if (!attr_set) {
        cudaFuncSetAttribute(cp_eval, cudaFuncAttributeMaxDynamicSharedMemorySize, SMEM_BYTES);
        attr_set = true;
    }
    cp_eval<<<NBLOCKS, BLK, SMEM_BYTES>>>(xyz, out);
}